// round 16
// baseline (speedup 1.0000x reference)
#include <cuda_runtime.h>
#include <math.h>

// compile-time capacities (actual dims taken from in_sizes/out_size at runtime)
#define MAXN 50000
#define MAXE 1600000
#define MAXT 12
#define MAXR (MAXT * MAXN)

// ---------------- scratch (static device memory; allocation-free) ----------------
__device__ int   d_is64;
__device__ float d_deg[MAXN];
__device__ float d_dinv[MAXN];
__device__ int   d_cnt[MAXN];
__device__ int   d_fill[MAXN];
__device__ int   d_rowptr[MAXN + 1];
__device__ int   d_esrc[MAXE];
__device__ float d_enorm[MAXE];
__device__ __align__(16) float d_Z[MAXR * 64];     // activations, ping
__device__ __align__(16) float d_ZW[MAXR * 64];    // activations, pong
__device__ __align__(16) float d_Xg[MAXR * 256];   // LSTM layer-0 pre-gates
__device__ __align__(16) float d_hlast[MAXN * 64];

// ---- fast transcendentals (sm_75+ tanh.approx: 1 MUFU, max abs err ~4.9e-4) ----
__device__ __forceinline__ float tanh_fast(float x) {
    float y;
    asm("tanh.approx.f32 %0, %1;" : "=f"(y) : "f"(x));
    return y;
}
__device__ __forceinline__ float sig_fast(float x) {
    return 0.5f + 0.5f * tanh_fast(0.5f * x);
}

// ---- packed fp32x2 FMA (sm_100+; ptxas never auto-fuses, must be inline PTX) ----
__device__ __forceinline__ unsigned long long pack2(float lo, float hi) {
    unsigned long long r;
    asm("mov.b64 %0, {%1, %2};" : "=l"(r) : "f"(lo), "f"(hi));
    return r;
}
__device__ __forceinline__ void unpack2(float& lo, float& hi, unsigned long long v) {
    asm("mov.b64 {%0, %1}, %2;" : "=f"(lo), "=f"(hi) : "l"(v));
}
__device__ __forceinline__ void fma2(unsigned long long& d, unsigned long long a,
                                     unsigned long long b) {
    asm("fma.rn.f32x2 %0, %1, %2, %0;" : "+l"(d) : "l"(a), "l"(b));
}

// ---- init: zero per-node arrays + dtype probe (src half only; always in-bounds) ----
__global__ void k_init(const int* __restrict__ ei32, int n, int e) {
    int i = blockIdx.x * blockDim.x + threadIdx.x;
    if (i < n) { d_deg[i] = 0.f; d_cnt[i] = 0; d_fill[i] = 0; }
    if (blockIdx.x == 0 && threadIdx.x == 0) {
        const long long* e64 = (const long long*)ei32;
        bool ok64 = true, ok32 = true;
        for (int s = 0; s < 256; s++) {
            long long idx = (e > 1) ? ((long long)s * (e - 1)) / 255 : 0;
            long long v64 = e64[idx];
            int v32 = ei32[idx];
            if (v64 < 0 || v64 >= n) ok64 = false;
            if (v32 < 0 || v32 >= n) ok32 = false;
        }
        d_is64 = ok64 ? 1 : (ok32 ? 0 : 1);
    }
}

__device__ __forceinline__ int edge_at(const void* ei, long long idx, int n) {
    int v = d_is64 ? (int)((const long long*)ei)[idx] : ((const int*)ei)[idx];
    return min(max(v, 0), n - 1);
}

__global__ void k_deg(const void* __restrict__ ei, const float* __restrict__ ew,
                      int n, int e) {
    int idx = blockIdx.x * blockDim.x + threadIdx.x;
    if (idx < e) {
        int dst = edge_at(ei, (long long)e + idx, n);
        atomicAdd(&d_deg[dst], ew[idx]);
        atomicAdd(&d_cnt[dst], 1);
    }
}

// ---- exclusive scan of counts -> rowptr, plus dinv (single block) ----
__global__ void k_scan2(int n) {
    __shared__ int s[1024];
    int tid = threadIdx.x;
    int CH = (n + 1023) >> 10;
    int start = tid * CH;
    for (int i = 0; i < CH; i++) {
        int idx = start + i;
        if (idx < n) d_dinv[idx] = rsqrtf(d_deg[idx] + 1.0f);
    }
    int sum = 0;
    for (int i = 0; i < CH; i++) { int idx = start + i; if (idx < n) sum += d_cnt[idx]; }
    s[tid] = sum;
    __syncthreads();
    for (int off = 1; off < 1024; off <<= 1) {
        int v = 0;
        if (tid >= off) v = s[tid - off];
        __syncthreads();
        if (tid >= off) s[tid] += v;
        __syncthreads();
    }
    int run = (tid == 0) ? 0 : s[tid - 1];
    for (int i = 0; i < CH; i++) {
        int idx = start + i;
        if (idx < n) { d_rowptr[idx] = run; run += d_cnt[idx]; }
    }
    if (tid == 1023) d_rowptr[n] = s[1023];
}

__global__ void k_fill(const void* __restrict__ ei, const float* __restrict__ ew,
                       int n, int e) {
    int idx = blockIdx.x * blockDim.x + threadIdx.x;
    if (idx < e) {
        int s = edge_at(ei, idx, n);
        int d = edge_at(ei, (long long)e + idx, n);
        int pos = d_rowptr[d] + atomicAdd(&d_fill[d], 1);
        pos = min(max(pos, 0), e - 1);
        d_esrc[pos] = s;
        d_enorm[pos] = d_dinv[s] * d_dinv[d] * ew[idx];
    }
}

// ---- fused: Z = relu(x @ W_in + b); ZW = Z @ gW0 (or write Z if no GCN) ----
__global__ __launch_bounds__(256) void k_projgemm(
    const float* __restrict__ x, const float* __restrict__ Win,
    const float* __restrict__ bin, const float* __restrict__ gW0,
    int rows, int fin, int doGemm) {
    __shared__ __align__(16) float xs[64][20];   // 80B row stride, 16B aligned
    __shared__ float Wi[16 * 64];
    __shared__ float bsh[64];
    __shared__ __align__(16) float Zs[64][68];
    __shared__ __align__(16) float Ws[64][68];
    int tid = threadIdx.x;
    int row0 = blockIdx.x * 64;
    for (int i = tid; i < 1024; i += 256) {
        int r = i >> 4, k = i & 15;
        int row = row0 + r;
        xs[r][k] = (k < fin && row < rows) ? x[(size_t)row * fin + k] : 0.f;
    }
    for (int i = tid; i < 1024; i += 256) Wi[i] = (i < fin * 64) ? Win[i] : 0.f;
    if (tid < 64) bsh[tid] = bin[tid];
    if (doGemm) {
        for (int i = tid; i < 1024; i += 256) {
            int k = i >> 4, kv = i & 15;
            *(float4*)&Ws[k][kv * 4] = *(const float4*)(gW0 + k * 64 + kv * 4);
        }
    }
    __syncthreads();
    {
        int r4 = tid >> 6, f = tid & 63;
        float wreg[16];
        #pragma unroll
        for (int k = 0; k < 16; k++) wreg[k] = Wi[k * 64 + f];
        #pragma unroll 4
        for (int rr = 0; rr < 16; rr++) {
            int r = rr * 4 + r4;
            float4 x0 = *(float4*)&xs[r][0];
            float4 x1 = *(float4*)&xs[r][4];
            float4 x2 = *(float4*)&xs[r][8];
            float4 x3 = *(float4*)&xs[r][12];
            float acc = bsh[f];
            acc = fmaf(x0.x, wreg[0], acc);  acc = fmaf(x0.y, wreg[1], acc);
            acc = fmaf(x0.z, wreg[2], acc);  acc = fmaf(x0.w, wreg[3], acc);
            acc = fmaf(x1.x, wreg[4], acc);  acc = fmaf(x1.y, wreg[5], acc);
            acc = fmaf(x1.z, wreg[6], acc);  acc = fmaf(x1.w, wreg[7], acc);
            acc = fmaf(x2.x, wreg[8], acc);  acc = fmaf(x2.y, wreg[9], acc);
            acc = fmaf(x2.z, wreg[10], acc); acc = fmaf(x2.w, wreg[11], acc);
            acc = fmaf(x3.x, wreg[12], acc); acc = fmaf(x3.y, wreg[13], acc);
            acc = fmaf(x3.z, wreg[14], acc); acc = fmaf(x3.w, wreg[15], acc);
            Zs[r][f] = fmaxf(acc, 0.f);
        }
    }
    __syncthreads();
    if (!doGemm) {
        int r4 = tid >> 6, f = tid & 63;
        for (int rr = 0; rr < 16; rr++) {
            int r = rr * 4 + r4;
            int row = row0 + r;
            if (row < rows) d_Z[(size_t)row * 64 + f] = Zs[r][f];
        }
        return;
    }
    int ty = tid >> 4, tx = tid & 15;
    unsigned long long a01[4] = {0, 0, 0, 0}, a23[4] = {0, 0, 0, 0};
    #pragma unroll 4
    for (int k4 = 0; k4 < 16; k4++) {
        unsigned long long wp[4][2];
        #pragma unroll
        for (int kk = 0; kk < 4; kk++) {
            float4 w = *(float4*)&Ws[k4 * 4 + kk][tx * 4];
            wp[kk][0] = pack2(w.x, w.y);
            wp[kk][1] = pack2(w.z, w.w);
        }
        #pragma unroll
        for (int i = 0; i < 4; i++) {
            float4 a4 = *(float4*)&Zs[ty * 4 + i][k4 * 4];
            unsigned long long hh;
            hh = pack2(a4.x, a4.x); fma2(a01[i], hh, wp[0][0]); fma2(a23[i], hh, wp[0][1]);
            hh = pack2(a4.y, a4.y); fma2(a01[i], hh, wp[1][0]); fma2(a23[i], hh, wp[1][1]);
            hh = pack2(a4.z, a4.z); fma2(a01[i], hh, wp[2][0]); fma2(a23[i], hh, wp[2][1]);
            hh = pack2(a4.w, a4.w); fma2(a01[i], hh, wp[3][0]); fma2(a23[i], hh, wp[3][1]);
        }
    }
    #pragma unroll
    for (int i = 0; i < 4; i++) {
        int row = row0 + ty * 4 + i;
        if (row < rows) {
            float4 o;
            unpack2(o.x, o.y, a01[i]);
            unpack2(o.z, o.w, a23[i]);
            *(float4*)(d_ZW + (size_t)row * 64 + tx * 4) = o;
        }
    }
}

// ---- ZW = Z @ W (64x64), f32x2, float4 A loads (R9 config) ----
__global__ __launch_bounds__(256) void k_gemm64(const float* __restrict__ W, int rows) {
    __shared__ __align__(16) float As[64][68];
    __shared__ __align__(16) float Ws[64][68];
    int tid = threadIdx.x;
    int row0 = blockIdx.x * 64;
    for (int i = tid; i < 1024; i += 256) {
        int r = i >> 4, kv = i & 15;
        float4 v = make_float4(0.f, 0.f, 0.f, 0.f);
        if (row0 + r < rows) v = *(const float4*)(d_Z + (size_t)(row0 + r) * 64 + kv * 4);
        *(float4*)&As[r][kv * 4] = v;
    }
    for (int i = tid; i < 1024; i += 256) {
        int k = i >> 4, kv = i & 15;
        *(float4*)&Ws[k][kv * 4] = *(const float4*)(W + k * 64 + kv * 4);
    }
    __syncthreads();
    int ty = tid >> 4, tx = tid & 15;
    unsigned long long a01[4] = {0, 0, 0, 0}, a23[4] = {0, 0, 0, 0};
    #pragma unroll 4
    for (int k4 = 0; k4 < 16; k4++) {
        unsigned long long wp[4][2];
        #pragma unroll
        for (int kk = 0; kk < 4; kk++) {
            float4 w = *(float4*)&Ws[k4 * 4 + kk][tx * 4];
            wp[kk][0] = pack2(w.x, w.y);
            wp[kk][1] = pack2(w.z, w.w);
        }
        #pragma unroll
        for (int i = 0; i < 4; i++) {
            float4 a4 = *(float4*)&As[ty * 4 + i][k4 * 4];
            unsigned long long hh;
            hh = pack2(a4.x, a4.x); fma2(a01[i], hh, wp[0][0]); fma2(a23[i], hh, wp[0][1]);
            hh = pack2(a4.y, a4.y); fma2(a01[i], hh, wp[1][0]); fma2(a23[i], hh, wp[1][1]);
            hh = pack2(a4.z, a4.z); fma2(a01[i], hh, wp[2][0]); fma2(a23[i], hh, wp[2][1]);
            hh = pack2(a4.w, a4.w); fma2(a01[i], hh, wp[3][0]); fma2(a23[i], hh, wp[3][1]);
        }
    }
    #pragma unroll
    for (int i = 0; i < 4; i++) {
        int row = row0 + ty * 4 + i;
        if (row < rows) {
            float4 o;
            unpack2(o.x, o.y, a01[i]);
            unpack2(o.z, o.w, a23[i]);
            *(float4*)(d_ZW + (size_t)row * 64 + tx * 4) = o;
        }
    }
}

// ---- GCN aggregation + bias + LayerNorm + ReLU : ZW -> Z ----
// 256-thread blocks: one node, 4 time-steps per block; edge tile shared in smem.
// R14 structure (2 barriers/tile); ONLY delta vs R14: gather unrolled x8.
__global__ __launch_bounds__(256) void k_gcn_agg(
    const float* __restrict__ gb, const float* __restrict__ lg,
    const float* __restrict__ lb, int n, int e, int T) {
    int node = blockIdx.x;
    int tid = threadIdx.x;
    int g = tid >> 6;                 // t-group 0..3
    int f = tid & 63;
    int t = blockIdx.y * 4 + g;
    bool act = (t < T);
    const float* zwt = d_ZW + (size_t)(act ? t : 0) * n * 64;
    __shared__ int   ss[64];
    __shared__ float sw[64];
    __shared__ float red[4][2];
    __shared__ float red2[4][2];
    float acc = 0.f;
    int st = min(max(d_rowptr[node], 0), e);
    int en = min(max(d_rowptr[node + 1], st), e);
    for (int base = st; base < en; base += 64) {
        __syncthreads();              // previous tile fully consumed
        if (tid < 64) {
            int ee = base + tid;
            if (ee < en) { ss[tid] = d_esrc[ee]; sw[tid] = d_enorm[ee]; }
        }
        __syncthreads();
        if (act) {
            int cnt = min(64, en - base);
            float p0 = 0.f, p1 = 0.f, p2 = 0.f, p3 = 0.f;
            float p4 = 0.f, p5 = 0.f, p6 = 0.f, p7 = 0.f;
            int j = 0;
            for (; j + 7 < cnt; j += 8) {
                p0 = fmaf(sw[j],     __ldg(&zwt[(size_t)ss[j]     * 64 + f]), p0);
                p1 = fmaf(sw[j + 1], __ldg(&zwt[(size_t)ss[j + 1] * 64 + f]), p1);
                p2 = fmaf(sw[j + 2], __ldg(&zwt[(size_t)ss[j + 2] * 64 + f]), p2);
                p3 = fmaf(sw[j + 3], __ldg(&zwt[(size_t)ss[j + 3] * 64 + f]), p3);
                p4 = fmaf(sw[j + 4], __ldg(&zwt[(size_t)ss[j + 4] * 64 + f]), p4);
                p5 = fmaf(sw[j + 5], __ldg(&zwt[(size_t)ss[j + 5] * 64 + f]), p5);
                p6 = fmaf(sw[j + 6], __ldg(&zwt[(size_t)ss[j + 6] * 64 + f]), p6);
                p7 = fmaf(sw[j + 7], __ldg(&zwt[(size_t)ss[j + 7] * 64 + f]), p7);
            }
            for (; j < cnt; j++)
                p0 = fmaf(sw[j], __ldg(&zwt[(size_t)ss[j] * 64 + f]), p0);
            acc += ((p0 + p1) + (p2 + p3)) + ((p4 + p5) + (p6 + p7));
        }
    }
    float dv = d_dinv[node];
    acc += dv * dv * zwt[(size_t)node * 64 + f] + gb[f];
    // LayerNorm over 64 features within each t-group (2 warps per group)
    int w2 = (tid >> 5) & 1;
    float v = acc;
    #pragma unroll
    for (int o = 16; o; o >>= 1) v += __shfl_xor_sync(0xffffffffu, v, o);
    if ((tid & 31) == 0) red[g][w2] = v;
    __syncthreads();
    float mean = (red[g][0] + red[g][1]) * (1.f / 64.f);
    float dd = acc - mean;
    float v2 = dd * dd;
    #pragma unroll
    for (int o = 16; o; o >>= 1) v2 += __shfl_xor_sync(0xffffffffu, v2, o);
    if ((tid & 31) == 0) red2[g][w2] = v2;
    __syncthreads();
    float var = (red2[g][0] + red2[g][1]) * (1.f / 64.f);
    float y = dd * rsqrtf(var + 1e-5f) * lg[f] + lb[f];
    if (act) d_Z[((size_t)t * n + node) * 64 + f] = fmaxf(y, 0.f);
}

// ---- Xg = Z @ Wih0^T + bih0 + bhh0  (f32x2; thread = 8 rows x 8 consecutive cols) ----
// smem: As 64x68 (17408B) + Ws 64x260 (66560B) + bs 256 (1024B) = 84992B
#define GATES_SMEM 84992
__global__ __launch_bounds__(256) void k_gates(const float* __restrict__ Wih,
                                               const float* __restrict__ bih,
                                               const float* __restrict__ bhh, int rows) {
    extern __shared__ __align__(16) float sm[];
    float* As = sm;              // [64][68]
    float* Ws = sm + 64 * 68;    // [64][260]  Ws[k][j] = Wih[j][k]
    float* bs = Ws + 64 * 260;   // [256]
    int tid = threadIdx.x;
    int row0 = blockIdx.x * 64;
    for (int i = tid; i < 1024; i += 256) {
        int r = i >> 4, kv = i & 15;
        float4 v = make_float4(0.f, 0.f, 0.f, 0.f);
        if (row0 + r < rows) v = *(const float4*)(d_Z + (size_t)(row0 + r) * 64 + kv * 4);
        *(float4*)&As[r * 68 + kv * 4] = v;
    }
    for (int i = tid; i < 16384; i += 256) {
        int j = i >> 6, k = i & 63;
        Ws[k * 260 + j] = Wih[i];
    }
    bs[tid] = bih[tid] + bhh[tid];
    __syncthreads();
    int ty = tid >> 5, tx = tid & 31;            // ty: 8 rows, tx: 8 consecutive cols
    unsigned long long acc[8][4];
    #pragma unroll
    for (int i = 0; i < 8; i++)
        #pragma unroll
        for (int p = 0; p < 4; p++) acc[i][p] = 0ULL;
    #pragma unroll 2
    for (int k = 0; k < 64; k++) {
        float4 wA = *(float4*)&Ws[k * 260 + tx * 8];
        float4 wB = *(float4*)&Ws[k * 260 + tx * 8 + 4];
        unsigned long long w0 = pack2(wA.x, wA.y), w1 = pack2(wA.z, wA.w);
        unsigned long long w2 = pack2(wB.x, wB.y), w3 = pack2(wB.z, wB.w);
        #pragma unroll
        for (int i = 0; i < 8; i++) {
            float a = As[(ty * 8 + i) * 68 + k];
            unsigned long long aa = pack2(a, a);
            fma2(acc[i][0], aa, w0);
            fma2(acc[i][1], aa, w1);
            fma2(acc[i][2], aa, w2);
            fma2(acc[i][3], aa, w3);
        }
    }
    float4 bA = make_float4(bs[tx * 8], bs[tx * 8 + 1], bs[tx * 8 + 2], bs[tx * 8 + 3]);
    float4 bB = make_float4(bs[tx * 8 + 4], bs[tx * 8 + 5], bs[tx * 8 + 6], bs[tx * 8 + 7]);
    #pragma unroll
    for (int i = 0; i < 8; i++) {
        int row = row0 + ty * 8 + i;
        if (row < rows) {
            float4 oA, oB;
            unpack2(oA.x, oA.y, acc[i][0]);
            unpack2(oA.z, oA.w, acc[i][1]);
            unpack2(oB.x, oB.y, acc[i][2]);
            unpack2(oB.z, oB.w, acc[i][3]);
            oA.x += bA.x; oA.y += bA.y; oA.z += bA.z; oA.w += bA.w;
            oB.x += bB.x; oB.y += bB.y; oB.z += bB.z; oB.w += bB.w;
            *(float4*)(d_Xg + (size_t)row * 256 + tx * 8) = oA;
            *(float4*)(d_Xg + (size_t)row * 256 + tx * 8 + 4) = oB;
        }
    }
}

// ---- 64x64 gate-packed h@W^T accumulate (8 rows/thread): float4 W + h broadcasts ----
__device__ __forceinline__ void mm64(const float4* __restrict__ Wm,
                                     const float* __restrict__ hs, int q, int f,
                                     unsigned long long* gxy, unsigned long long* gzw) {
    #pragma unroll 4
    for (int k4 = 0; k4 < 16; k4++) {
        unsigned long long wp[4][2];
        #pragma unroll
        for (int kk = 0; kk < 4; kk++) {
            float4 w = Wm[(k4 * 4 + kk) * 64 + f];
            wp[kk][0] = pack2(w.x, w.y);
            wp[kk][1] = pack2(w.z, w.w);
        }
        #pragma unroll
        for (int i = 0; i < 8; i++) {
            float4 h4 = *(const float4*)&hs[(q * 8 + i) * 64 + k4 * 4];
            unsigned long long hh;
            hh = pack2(h4.x, h4.x); fma2(gxy[i], hh, wp[0][0]); fma2(gzw[i], hh, wp[0][1]);
            hh = pack2(h4.y, h4.y); fma2(gxy[i], hh, wp[1][0]); fma2(gzw[i], hh, wp[1][1]);
            hh = pack2(h4.z, h4.z); fma2(gxy[i], hh, wp[2][0]); fma2(gzw[i], hh, wp[2][1]);
            hh = pack2(h4.w, h4.w); fma2(gxy[i], hh, wp[3][0]); fma2(gzw[i], hh, wp[3][1]);
        }
    }
}

// ---- fused 2-layer LSTM (T steps), 512 threads, 8 rows/thread (R9 config) ----
// dynamic SMEM: 3 * 4096 * 16B + 2 * 4096 * 4B = 229376 bytes
#define LSTM_SMEM 229376
__global__ __launch_bounds__(512) void k_lstm(
    const float* __restrict__ Whh0, const float* __restrict__ Wih1,
    const float* __restrict__ Whh1, const float* __restrict__ bih1,
    const float* __restrict__ bhh1, int n, int T) {
    extern __shared__ __align__(16) float smem[];
    float4* W0s = (float4*)smem;         // [64][64] gate-packed (i,f,g,o), 64KB
    float4* W1i = W0s + 4096;            // 64KB
    float4* W1h = W1i + 4096;            // 64KB
    float* h0s = (float*)(W1h + 4096);   // [64 rows][64], 16KB
    float* h1s = h0s + 64 * 64;          // 16KB
    int tid = threadIdx.x;
    int f = tid & 63, q = tid >> 6;      // q in 0..7, 8 rows each
    for (int idx = tid; idx < 4096; idx += 512) {
        int k = idx >> 6, j = idx & 63;
        W0s[k * 64 + j] = make_float4(Whh0[j * 64 + k], Whh0[(j + 64) * 64 + k],
                                      Whh0[(j + 128) * 64 + k], Whh0[(j + 192) * 64 + k]);
        W1i[k * 64 + j] = make_float4(Wih1[j * 64 + k], Wih1[(j + 64) * 64 + k],
                                      Wih1[(j + 128) * 64 + k], Wih1[(j + 192) * 64 + k]);
        W1h[k * 64 + j] = make_float4(Whh1[j * 64 + k], Whh1[(j + 64) * 64 + k],
                                      Whh1[(j + 128) * 64 + k], Whh1[(j + 192) * 64 + k]);
    }
    for (int idx = tid; idx < 4096; idx += 512) { h0s[idx] = 0.f; h1s[idx] = 0.f; }
    unsigned long long b1xy = pack2(bih1[f] + bhh1[f], bih1[64 + f] + bhh1[64 + f]);
    unsigned long long b1zw = pack2(bih1[128 + f] + bhh1[128 + f],
                                    bih1[192 + f] + bhh1[192 + f]);
    float c0[8], c1[8];
    #pragma unroll
    for (int i = 0; i < 8; i++) { c0[i] = 0.f; c1[i] = 0.f; }
    int row0 = blockIdx.x * 64;
    __syncthreads();
    for (int t = 0; t < T; t++) {
        const float* Xgt = d_Xg + ((size_t)t * n + row0) * 256;
        // prefetch this step's x-gates into registers (hidden under mm64 below)
        float xg[8][4];
        #pragma unroll
        for (int i = 0; i < 8; i++) {
            bool ok = (row0 + q * 8 + i) < n;
            const float* p = Xgt + (q * 8 + i) * 256;
            xg[i][0] = ok ? p[f] : 0.f;
            xg[i][1] = ok ? p[64 + f] : 0.f;
            xg[i][2] = ok ? p[128 + f] : 0.f;
            xg[i][3] = ok ? p[192 + f] : 0.f;
        }
        // ---- layer 0: g = h0 @ Whh0^T ----
        unsigned long long gxy[8], gzw[8];
        #pragma unroll
        for (int i = 0; i < 8; i++) { gxy[i] = 0ULL; gzw[i] = 0ULL; }
        mm64(W0s, h0s, q, f, gxy, gzw);
        __syncthreads();  // reads of h0s done before overwrite
        #pragma unroll
        for (int i = 0; i < 8; i++) {
            float gi, gf, gg, go;
            unpack2(gi, gf, gxy[i]);
            unpack2(gg, go, gzw[i]);
            float zi = xg[i][0] + gi, zf = xg[i][1] + gf;
            float zg = xg[i][2] + gg, zo = xg[i][3] + go;
            float cn = sig_fast(zf) * c0[i] + sig_fast(zi) * tanh_fast(zg);
            c0[i] = cn;
            h0s[(q * 8 + i) * 64 + f] = sig_fast(zo) * tanh_fast(cn);
        }
        __syncthreads();  // h0 ready for layer 1
        // ---- layer 1: g = h0 @ Wih1^T + h1 @ Whh1^T + b1 ----
        #pragma unroll
        for (int i = 0; i < 8; i++) { gxy[i] = b1xy; gzw[i] = b1zw; }
        mm64(W1i, h0s, q, f, gxy, gzw);
        mm64(W1h, h1s, q, f, gxy, gzw);
        __syncthreads();  // reads of h1s done before overwrite
        #pragma unroll
        for (int i = 0; i < 8; i++) {
            float gi, gf, gg, go;
            unpack2(gi, gf, gxy[i]);
            unpack2(gg, go, gzw[i]);
            float cn = sig_fast(gf) * c1[i] + sig_fast(gi) * tanh_fast(gg);
            c1[i] = cn;
            h1s[(q * 8 + i) * 64 + f] = sig_fast(go) * tanh_fast(cn);
        }
        __syncthreads();  // h1 ready for next t
    }
    #pragma unroll
    for (int i = 0; i < 8; i++) {
        int grow = row0 + q * 8 + i;
        if (grow < n) d_hlast[(size_t)grow * 64 + f] = h1s[(q * 8 + i) * 64 + f];
    }
}

// ---- head: out = relu(h_last @ fc1 + b1) @ fc2 + b2 ----
__global__ void k_head(const float* __restrict__ f1W, const float* __restrict__ f1b,
                       const float* __restrict__ f2W, const float* __restrict__ f2b,
                       float* __restrict__ out, int n) {
    int warp = threadIdx.x >> 5, lane = threadIdx.x & 31;
    int row = blockIdx.x * 4 + warp;
    if (row >= n) return;
    const float* hr = d_hlast + (size_t)row * 64;
    float acc = f1b[lane];
    #pragma unroll 8
    for (int k = 0; k < 64; k++) acc = fmaf(hr[k], f1W[k * 32 + lane], acc);
    float v = fmaxf(acc, 0.f) * f2W[lane];
    #pragma unroll
    for (int o = 16; o; o >>= 1) v += __shfl_xor_sync(0xffffffffu, v, o);
    if (lane == 0) out[row] = v + f2b[0];
}

// ---------------- launch ----------------
extern "C" void kernel_launch(void* const* d_in, const int* in_sizes, int n_in,
                              void* d_out, int out_size) {
    const float* x    = (const float*)d_in[0];
    const void*  ei   = d_in[1];               // int32 or int64, detected on device
    const float* ew   = (const float*)d_in[2];
    const float* Win  = (const float*)d_in[3];
    const float* bin  = (const float*)d_in[4];
    const float* gW   = (const float*)d_in[5];
    const float* gb   = (const float*)d_in[6];
    const float* lng  = (const float*)d_in[7];
    const float* lnb  = (const float*)d_in[8];
    const float* Wih0 = (const float*)d_in[9];
    const float* Whh0 = (const float*)d_in[10];
    const float* bih0 = (const float*)d_in[11];
    const float* bhh0 = (const float*)d_in[12];
    const float* Wih1 = (const float*)d_in[13];
    const float* Whh1 = (const float*)d_in[14];
    const float* bih1 = (const float*)d_in[15];
    const float* bhh1 = (const float*)d_in[16];
    const float* f1W  = (const float*)d_in[17];
    const float* f1b  = (const float*)d_in[18];
    const float* f2W  = (const float*)d_in[19];
    const float* f2b  = (const float*)d_in[20];
    float* out = (float*)d_out;

    // runtime shapes (clamped to static capacity)
    int n = out_size;                         // B*N with B=1
    if (n > MAXN) n = MAXN;
    int e = in_sizes[2];                      // edge count from edge_weight
    if (e > MAXE) e = MAXE;
    int fin = in_sizes[3] / 64;               // W_in: (F_IN, 64)
    if (fin > 16) fin = 16;
    int rows = in_sizes[0] / (fin > 0 ? fin : 1);  // T * N
    if (rows > MAXR) rows = MAXR;
    int T = rows / (n > 0 ? n : 1);
    if (T > MAXT) T = MAXT;
    int ngcn = in_sizes[5] / 4096;            // gcn_W: (L, 64, 64)

    cudaFuncSetAttribute(k_gates, cudaFuncAttributeMaxDynamicSharedMemorySize, GATES_SMEM);
    cudaFuncSetAttribute(k_lstm, cudaFuncAttributeMaxDynamicSharedMemorySize, LSTM_SMEM);

    // side stream + events, lazily created once (resource creation only — the
    // captured/executed GPU work is identical on every call)
    static cudaStream_t s2 = 0;
    static cudaEvent_t evF = 0, evJ = 0;
    if (s2 == 0) {
        cudaStreamCreateWithFlags(&s2, cudaStreamNonBlocking);
        cudaEventCreateWithFlags(&evF, cudaEventDisableTiming);
        cudaEventCreateWithFlags(&evJ, cudaEventDisableTiming);
    }

    // fork: CSR build on s2, projgemm on main stream (fully independent)
    cudaEventRecord(evF, 0);
    cudaStreamWaitEvent(s2, evF, 0);
    k_init<<<(n + 255) / 256, 256, 0, s2>>>((const int*)ei, n, e);
    k_deg<<<(e + 255) / 256, 256, 0, s2>>>(ei, ew, n, e);
    k_scan2<<<1, 1024, 0, s2>>>(n);
    k_fill<<<(e + 255) / 256, 256, 0, s2>>>(ei, ew, n, e);
    cudaEventRecord(evJ, s2);

    // fused input projection + GCN layer-0 GEMM (main stream, overlaps CSR)
    k_projgemm<<<(rows + 63) / 64, 256>>>(x, Win, bin, gW, rows, fin, ngcn > 0 ? 1 : 0);

    // join: first aggregation needs BOTH the CSR and the projected features
    cudaStreamWaitEvent(0, evJ, 0);

    // GCN layers (quad-t aggregation — R14 structure, unroll-8 gather)
    for (int l = 0; l < ngcn; l++) {
        if (l > 0) k_gemm64<<<(rows + 63) / 64, 256>>>(gW + (size_t)l * 4096, rows);
        k_gcn_agg<<<dim3(n, (T + 3) / 4), 256>>>(gb + l * 64, lng + l * 64, lnb + l * 64,
                                                 n, e, T);
    }

    // LSTM layer-0 input gates (batched over all t)
    k_gates<<<(rows + 63) / 64, 256, GATES_SMEM>>>(Wih0, bih0, bhh0, rows);
    // fused 2-layer, T-step recurrence (512 threads, 8 rows/thread — R9 config)
    k_lstm<<<(n + 63) / 64, 512, LSTM_SMEM>>>(Whh0, Wih1, Whh1, bih1, bhh1, n, T);

    // head
    k_head<<<(n + 3) / 4, 128>>>(f1W, f1b, f2W, f2b, out, n);
}

// round 17
// speedup vs baseline: 1.0518x; 1.0518x over previous
#include <cuda_runtime.h>
#include <math.h>

// compile-time capacities (actual dims taken from in_sizes/out_size at runtime)
#define MAXN 50000
#define MAXE 1600000
#define MAXT 12
#define MAXR (MAXT * MAXN)

// ---------------- scratch (static device memory; allocation-free) ----------------
__device__ int   d_is64;
__device__ float d_deg[MAXN];
__device__ float d_dinv[MAXN];
__device__ int   d_cnt[MAXN];
__device__ int   d_fill[MAXN];
__device__ int   d_rowptr[MAXN + 1];
__device__ int   d_esrc[MAXE];
__device__ float d_enorm[MAXE];
__device__ __align__(16) float d_Z[MAXR * 64];     // activations, ping
__device__ __align__(16) float d_ZW[MAXR * 64];    // activations, pong
__device__ __align__(16) float d_Xg[MAXR * 256];   // LSTM layer-0 pre-gates
__device__ __align__(16) float d_hlast[MAXN * 64];

// ---- fast transcendentals (sm_75+ tanh.approx: 1 MUFU, max abs err ~4.9e-4) ----
__device__ __forceinline__ float tanh_fast(float x) {
    float y;
    asm("tanh.approx.f32 %0, %1;" : "=f"(y) : "f"(x));
    return y;
}
__device__ __forceinline__ float sig_fast(float x) {
    return 0.5f + 0.5f * tanh_fast(0.5f * x);
}

// ---- packed fp32x2 FMA (sm_100+; ptxas never auto-fuses, must be inline PTX) ----
__device__ __forceinline__ unsigned long long pack2(float lo, float hi) {
    unsigned long long r;
    asm("mov.b64 %0, {%1, %2};" : "=l"(r) : "f"(lo), "f"(hi));
    return r;
}
__device__ __forceinline__ void unpack2(float& lo, float& hi, unsigned long long v) {
    asm("mov.b64 {%0, %1}, %2;" : "=f"(lo), "=f"(hi) : "l"(v));
}
__device__ __forceinline__ void fma2(unsigned long long& d, unsigned long long a,
                                     unsigned long long b) {
    asm("fma.rn.f32x2 %0, %1, %2, %0;" : "+l"(d) : "l"(a), "l"(b));
}

// ---- init: zero per-node arrays + dtype probe (src half only; always in-bounds) ----
__global__ void k_init(const int* __restrict__ ei32, int n, int e) {
    int i = blockIdx.x * blockDim.x + threadIdx.x;
    if (i < n) { d_deg[i] = 0.f; d_cnt[i] = 0; d_fill[i] = 0; }
    if (blockIdx.x == 0 && threadIdx.x == 0) {
        const long long* e64 = (const long long*)ei32;
        bool ok64 = true, ok32 = true;
        for (int s = 0; s < 256; s++) {
            long long idx = (e > 1) ? ((long long)s * (e - 1)) / 255 : 0;
            long long v64 = e64[idx];
            int v32 = ei32[idx];
            if (v64 < 0 || v64 >= n) ok64 = false;
            if (v32 < 0 || v32 >= n) ok32 = false;
        }
        d_is64 = ok64 ? 1 : (ok32 ? 0 : 1);
    }
}

__device__ __forceinline__ int edge_at(const void* ei, long long idx, int n) {
    int v = d_is64 ? (int)((const long long*)ei)[idx] : ((const int*)ei)[idx];
    return min(max(v, 0), n - 1);
}

__global__ void k_deg(const void* __restrict__ ei, const float* __restrict__ ew,
                      int n, int e) {
    int idx = blockIdx.x * blockDim.x + threadIdx.x;
    if (idx < e) {
        int dst = edge_at(ei, (long long)e + idx, n);
        atomicAdd(&d_deg[dst], ew[idx]);
        atomicAdd(&d_cnt[dst], 1);
    }
}

// ---- exclusive scan of counts -> rowptr, plus dinv (single block) ----
__global__ void k_scan2(int n) {
    __shared__ int s[1024];
    int tid = threadIdx.x;
    int CH = (n + 1023) >> 10;
    int start = tid * CH;
    for (int i = 0; i < CH; i++) {
        int idx = start + i;
        if (idx < n) d_dinv[idx] = rsqrtf(d_deg[idx] + 1.0f);
    }
    int sum = 0;
    for (int i = 0; i < CH; i++) { int idx = start + i; if (idx < n) sum += d_cnt[idx]; }
    s[tid] = sum;
    __syncthreads();
    for (int off = 1; off < 1024; off <<= 1) {
        int v = 0;
        if (tid >= off) v = s[tid - off];
        __syncthreads();
        if (tid >= off) s[tid] += v;
        __syncthreads();
    }
    int run = (tid == 0) ? 0 : s[tid - 1];
    for (int i = 0; i < CH; i++) {
        int idx = start + i;
        if (idx < n) { d_rowptr[idx] = run; run += d_cnt[idx]; }
    }
    if (tid == 1023) d_rowptr[n] = s[1023];
}

__global__ void k_fill(const void* __restrict__ ei, const float* __restrict__ ew,
                       int n, int e) {
    int idx = blockIdx.x * blockDim.x + threadIdx.x;
    if (idx < e) {
        int s = edge_at(ei, idx, n);
        int d = edge_at(ei, (long long)e + idx, n);
        int pos = d_rowptr[d] + atomicAdd(&d_fill[d], 1);
        pos = min(max(pos, 0), e - 1);
        d_esrc[pos] = s;
        d_enorm[pos] = d_dinv[s] * d_dinv[d] * ew[idx];
    }
}

// ---- fused: Z = relu(x @ W_in + b); ZW = Z @ gW0 (or write Z if no GCN) ----
__global__ __launch_bounds__(256) void k_projgemm(
    const float* __restrict__ x, const float* __restrict__ Win,
    const float* __restrict__ bin, const float* __restrict__ gW0,
    int rows, int fin, int doGemm) {
    __shared__ __align__(16) float xs[64][20];   // 80B row stride, 16B aligned
    __shared__ float Wi[16 * 64];
    __shared__ float bsh[64];
    __shared__ __align__(16) float Zs[64][68];
    __shared__ __align__(16) float Ws[64][68];
    int tid = threadIdx.x;
    int row0 = blockIdx.x * 64;
    for (int i = tid; i < 1024; i += 256) {
        int r = i >> 4, k = i & 15;
        int row = row0 + r;
        xs[r][k] = (k < fin && row < rows) ? x[(size_t)row * fin + k] : 0.f;
    }
    for (int i = tid; i < 1024; i += 256) Wi[i] = (i < fin * 64) ? Win[i] : 0.f;
    if (tid < 64) bsh[tid] = bin[tid];
    if (doGemm) {
        for (int i = tid; i < 1024; i += 256) {
            int k = i >> 4, kv = i & 15;
            *(float4*)&Ws[k][kv * 4] = *(const float4*)(gW0 + k * 64 + kv * 4);
        }
    }
    __syncthreads();
    {
        int r4 = tid >> 6, f = tid & 63;
        float wreg[16];
        #pragma unroll
        for (int k = 0; k < 16; k++) wreg[k] = Wi[k * 64 + f];
        #pragma unroll 4
        for (int rr = 0; rr < 16; rr++) {
            int r = rr * 4 + r4;
            float4 x0 = *(float4*)&xs[r][0];
            float4 x1 = *(float4*)&xs[r][4];
            float4 x2 = *(float4*)&xs[r][8];
            float4 x3 = *(float4*)&xs[r][12];
            float acc = bsh[f];
            acc = fmaf(x0.x, wreg[0], acc);  acc = fmaf(x0.y, wreg[1], acc);
            acc = fmaf(x0.z, wreg[2], acc);  acc = fmaf(x0.w, wreg[3], acc);
            acc = fmaf(x1.x, wreg[4], acc);  acc = fmaf(x1.y, wreg[5], acc);
            acc = fmaf(x1.z, wreg[6], acc);  acc = fmaf(x1.w, wreg[7], acc);
            acc = fmaf(x2.x, wreg[8], acc);  acc = fmaf(x2.y, wreg[9], acc);
            acc = fmaf(x2.z, wreg[10], acc); acc = fmaf(x2.w, wreg[11], acc);
            acc = fmaf(x3.x, wreg[12], acc); acc = fmaf(x3.y, wreg[13], acc);
            acc = fmaf(x3.z, wreg[14], acc); acc = fmaf(x3.w, wreg[15], acc);
            Zs[r][f] = fmaxf(acc, 0.f);
        }
    }
    __syncthreads();
    if (!doGemm) {
        int r4 = tid >> 6, f = tid & 63;
        for (int rr = 0; rr < 16; rr++) {
            int r = rr * 4 + r4;
            int row = row0 + r;
            if (row < rows) d_Z[(size_t)row * 64 + f] = Zs[r][f];
        }
        return;
    }
    int ty = tid >> 4, tx = tid & 15;
    unsigned long long a01[4] = {0, 0, 0, 0}, a23[4] = {0, 0, 0, 0};
    #pragma unroll 4
    for (int k4 = 0; k4 < 16; k4++) {
        unsigned long long wp[4][2];
        #pragma unroll
        for (int kk = 0; kk < 4; kk++) {
            float4 w = *(float4*)&Ws[k4 * 4 + kk][tx * 4];
            wp[kk][0] = pack2(w.x, w.y);
            wp[kk][1] = pack2(w.z, w.w);
        }
        #pragma unroll
        for (int i = 0; i < 4; i++) {
            float4 a4 = *(float4*)&Zs[ty * 4 + i][k4 * 4];
            unsigned long long hh;
            hh = pack2(a4.x, a4.x); fma2(a01[i], hh, wp[0][0]); fma2(a23[i], hh, wp[0][1]);
            hh = pack2(a4.y, a4.y); fma2(a01[i], hh, wp[1][0]); fma2(a23[i], hh, wp[1][1]);
            hh = pack2(a4.z, a4.z); fma2(a01[i], hh, wp[2][0]); fma2(a23[i], hh, wp[2][1]);
            hh = pack2(a4.w, a4.w); fma2(a01[i], hh, wp[3][0]); fma2(a23[i], hh, wp[3][1]);
        }
    }
    #pragma unroll
    for (int i = 0; i < 4; i++) {
        int row = row0 + ty * 4 + i;
        if (row < rows) {
            float4 o;
            unpack2(o.x, o.y, a01[i]);
            unpack2(o.z, o.w, a23[i]);
            *(float4*)(d_ZW + (size_t)row * 64 + tx * 4) = o;
        }
    }
}

// ---- ZW = Z @ W (64x64), f32x2, float4 A loads (R9 config) ----
__global__ __launch_bounds__(256) void k_gemm64(const float* __restrict__ W, int rows) {
    __shared__ __align__(16) float As[64][68];
    __shared__ __align__(16) float Ws[64][68];
    int tid = threadIdx.x;
    int row0 = blockIdx.x * 64;
    for (int i = tid; i < 1024; i += 256) {
        int r = i >> 4, kv = i & 15;
        float4 v = make_float4(0.f, 0.f, 0.f, 0.f);
        if (row0 + r < rows) v = *(const float4*)(d_Z + (size_t)(row0 + r) * 64 + kv * 4);
        *(float4*)&As[r][kv * 4] = v;
    }
    for (int i = tid; i < 1024; i += 256) {
        int k = i >> 4, kv = i & 15;
        *(float4*)&Ws[k][kv * 4] = *(const float4*)(W + k * 64 + kv * 4);
    }
    __syncthreads();
    int ty = tid >> 4, tx = tid & 15;
    unsigned long long a01[4] = {0, 0, 0, 0}, a23[4] = {0, 0, 0, 0};
    #pragma unroll 4
    for (int k4 = 0; k4 < 16; k4++) {
        unsigned long long wp[4][2];
        #pragma unroll
        for (int kk = 0; kk < 4; kk++) {
            float4 w = *(float4*)&Ws[k4 * 4 + kk][tx * 4];
            wp[kk][0] = pack2(w.x, w.y);
            wp[kk][1] = pack2(w.z, w.w);
        }
        #pragma unroll
        for (int i = 0; i < 4; i++) {
            float4 a4 = *(float4*)&As[ty * 4 + i][k4 * 4];
            unsigned long long hh;
            hh = pack2(a4.x, a4.x); fma2(a01[i], hh, wp[0][0]); fma2(a23[i], hh, wp[0][1]);
            hh = pack2(a4.y, a4.y); fma2(a01[i], hh, wp[1][0]); fma2(a23[i], hh, wp[1][1]);
            hh = pack2(a4.z, a4.z); fma2(a01[i], hh, wp[2][0]); fma2(a23[i], hh, wp[2][1]);
            hh = pack2(a4.w, a4.w); fma2(a01[i], hh, wp[3][0]); fma2(a23[i], hh, wp[3][1]);
        }
    }
    #pragma unroll
    for (int i = 0; i < 4; i++) {
        int row = row0 + ty * 4 + i;
        if (row < rows) {
            float4 o;
            unpack2(o.x, o.y, a01[i]);
            unpack2(o.z, o.w, a23[i]);
            *(float4*)(d_ZW + (size_t)row * 64 + tx * 4) = o;
        }
    }
}

// ---- GCN aggregation + bias + LayerNorm + ReLU : ZW -> Z ----
// 256-thread blocks: one node, 4 time-steps per block; edge tile shared in smem.
// (R14 configuration — empirical best: unroll-4 gather, 2 barriers/tile)
__global__ __launch_bounds__(256) void k_gcn_agg(
    const float* __restrict__ gb, const float* __restrict__ lg,
    const float* __restrict__ lb, int n, int e, int T) {
    int node = blockIdx.x;
    int tid = threadIdx.x;
    int g = tid >> 6;                 // t-group 0..3
    int f = tid & 63;
    int t = blockIdx.y * 4 + g;
    bool act = (t < T);
    const float* zwt = d_ZW + (size_t)(act ? t : 0) * n * 64;
    __shared__ int   ss[64];
    __shared__ float sw[64];
    __shared__ float red[4][2];
    __shared__ float red2[4][2];
    float acc = 0.f;
    int st = min(max(d_rowptr[node], 0), e);
    int en = min(max(d_rowptr[node + 1], st), e);
    for (int base = st; base < en; base += 64) {
        __syncthreads();              // previous tile fully consumed
        if (tid < 64) {
            int ee = base + tid;
            if (ee < en) { ss[tid] = d_esrc[ee]; sw[tid] = d_enorm[ee]; }
        }
        __syncthreads();
        if (act) {
            int cnt = min(64, en - base);
            float p0 = 0.f, p1 = 0.f, p2 = 0.f, p3 = 0.f;
            int j = 0;
            for (; j + 3 < cnt; j += 4) {
                p0 += sw[j]     * __ldg(&zwt[(size_t)ss[j]     * 64 + f]);
                p1 += sw[j + 1] * __ldg(&zwt[(size_t)ss[j + 1] * 64 + f]);
                p2 += sw[j + 2] * __ldg(&zwt[(size_t)ss[j + 2] * 64 + f]);
                p3 += sw[j + 3] * __ldg(&zwt[(size_t)ss[j + 3] * 64 + f]);
            }
            for (; j < cnt; j++) p0 += sw[j] * __ldg(&zwt[(size_t)ss[j] * 64 + f]);
            acc += (p0 + p1) + (p2 + p3);
        }
    }
    float dv = d_dinv[node];
    acc += dv * dv * zwt[(size_t)node * 64 + f] + gb[f];
    // LayerNorm over 64 features within each t-group (2 warps per group)
    int w2 = (tid >> 5) & 1;
    float v = acc;
    #pragma unroll
    for (int o = 16; o; o >>= 1) v += __shfl_xor_sync(0xffffffffu, v, o);
    if ((tid & 31) == 0) red[g][w2] = v;
    __syncthreads();
    float mean = (red[g][0] + red[g][1]) * (1.f / 64.f);
    float dd = acc - mean;
    float v2 = dd * dd;
    #pragma unroll
    for (int o = 16; o; o >>= 1) v2 += __shfl_xor_sync(0xffffffffu, v2, o);
    if ((tid & 31) == 0) red2[g][w2] = v2;
    __syncthreads();
    float var = (red2[g][0] + red2[g][1]) * (1.f / 64.f);
    float y = dd * rsqrtf(var + 1e-5f) * lg[f] + lb[f];
    if (act) d_Z[((size_t)t * n + node) * 64 + f] = fmaxf(y, 0.f);
}

// ---- Xg = Z @ Wih0^T + bih0 + bhh0  (f32x2; thread = 8 rows x 8 consecutive cols) ----
// smem: As 64x68 (17408B) + Ws 64x260 (66560B) + bs 256 (1024B) = 84992B
#define GATES_SMEM 84992
__global__ __launch_bounds__(256) void k_gates(const float* __restrict__ Wih,
                                               const float* __restrict__ bih,
                                               const float* __restrict__ bhh, int rows) {
    extern __shared__ __align__(16) float sm[];
    float* As = sm;              // [64][68]
    float* Ws = sm + 64 * 68;    // [64][260]  Ws[k][j] = Wih[j][k]
    float* bs = Ws + 64 * 260;   // [256]
    int tid = threadIdx.x;
    int row0 = blockIdx.x * 64;
    for (int i = tid; i < 1024; i += 256) {
        int r = i >> 4, kv = i & 15;
        float4 v = make_float4(0.f, 0.f, 0.f, 0.f);
        if (row0 + r < rows) v = *(const float4*)(d_Z + (size_t)(row0 + r) * 64 + kv * 4);
        *(float4*)&As[r * 68 + kv * 4] = v;
    }
    for (int i = tid; i < 16384; i += 256) {
        int j = i >> 6, k = i & 63;
        Ws[k * 260 + j] = Wih[i];
    }
    bs[tid] = bih[tid] + bhh[tid];
    __syncthreads();
    int ty = tid >> 5, tx = tid & 31;            // ty: 8 rows, tx: 8 consecutive cols
    unsigned long long acc[8][4];
    #pragma unroll
    for (int i = 0; i < 8; i++)
        #pragma unroll
        for (int p = 0; p < 4; p++) acc[i][p] = 0ULL;
    #pragma unroll 2
    for (int k = 0; k < 64; k++) {
        float4 wA = *(float4*)&Ws[k * 260 + tx * 8];
        float4 wB = *(float4*)&Ws[k * 260 + tx * 8 + 4];
        unsigned long long w0 = pack2(wA.x, wA.y), w1 = pack2(wA.z, wA.w);
        unsigned long long w2 = pack2(wB.x, wB.y), w3 = pack2(wB.z, wB.w);
        #pragma unroll
        for (int i = 0; i < 8; i++) {
            float a = As[(ty * 8 + i) * 68 + k];
            unsigned long long aa = pack2(a, a);
            fma2(acc[i][0], aa, w0);
            fma2(acc[i][1], aa, w1);
            fma2(acc[i][2], aa, w2);
            fma2(acc[i][3], aa, w3);
        }
    }
    float4 bA = make_float4(bs[tx * 8], bs[tx * 8 + 1], bs[tx * 8 + 2], bs[tx * 8 + 3]);
    float4 bB = make_float4(bs[tx * 8 + 4], bs[tx * 8 + 5], bs[tx * 8 + 6], bs[tx * 8 + 7]);
    #pragma unroll
    for (int i = 0; i < 8; i++) {
        int row = row0 + ty * 8 + i;
        if (row < rows) {
            float4 oA, oB;
            unpack2(oA.x, oA.y, acc[i][0]);
            unpack2(oA.z, oA.w, acc[i][1]);
            unpack2(oB.x, oB.y, acc[i][2]);
            unpack2(oB.z, oB.w, acc[i][3]);
            oA.x += bA.x; oA.y += bA.y; oA.z += bA.z; oA.w += bA.w;
            oB.x += bB.x; oB.y += bB.y; oB.z += bB.z; oB.w += bB.w;
            *(float4*)(d_Xg + (size_t)row * 256 + tx * 8) = oA;
            *(float4*)(d_Xg + (size_t)row * 256 + tx * 8 + 4) = oB;
        }
    }
}

// ---- 64x64 gate-packed h@W^T accumulate (8 rows/thread): float4 W + h broadcasts ----
__device__ __forceinline__ void mm64(const float4* __restrict__ Wm,
                                     const float* __restrict__ hs, int q, int f,
                                     unsigned long long* gxy, unsigned long long* gzw) {
    #pragma unroll 4
    for (int k4 = 0; k4 < 16; k4++) {
        unsigned long long wp[4][2];
        #pragma unroll
        for (int kk = 0; kk < 4; kk++) {
            float4 w = Wm[(k4 * 4 + kk) * 64 + f];
            wp[kk][0] = pack2(w.x, w.y);
            wp[kk][1] = pack2(w.z, w.w);
        }
        #pragma unroll
        for (int i = 0; i < 8; i++) {
            float4 h4 = *(const float4*)&hs[(q * 8 + i) * 64 + k4 * 4];
            unsigned long long hh;
            hh = pack2(h4.x, h4.x); fma2(gxy[i], hh, wp[0][0]); fma2(gzw[i], hh, wp[0][1]);
            hh = pack2(h4.y, h4.y); fma2(gxy[i], hh, wp[1][0]); fma2(gzw[i], hh, wp[1][1]);
            hh = pack2(h4.z, h4.z); fma2(gxy[i], hh, wp[2][0]); fma2(gzw[i], hh, wp[2][1]);
            hh = pack2(h4.w, h4.w); fma2(gxy[i], hh, wp[3][0]); fma2(gzw[i], hh, wp[3][1]);
        }
    }
}

// ---- fused 2-layer LSTM (T steps), 512 threads, 8 rows/thread (R9 config) ----
// dynamic SMEM: 3 * 4096 * 16B + 2 * 4096 * 4B = 229376 bytes
#define LSTM_SMEM 229376
__global__ __launch_bounds__(512) void k_lstm(
    const float* __restrict__ Whh0, const float* __restrict__ Wih1,
    const float* __restrict__ Whh1, const float* __restrict__ bih1,
    const float* __restrict__ bhh1, int n, int T) {
    extern __shared__ __align__(16) float smem[];
    float4* W0s = (float4*)smem;         // [64][64] gate-packed (i,f,g,o), 64KB
    float4* W1i = W0s + 4096;            // 64KB
    float4* W1h = W1i + 4096;            // 64KB
    float* h0s = (float*)(W1h + 4096);   // [64 rows][64], 16KB
    float* h1s = h0s + 64 * 64;          // 16KB
    int tid = threadIdx.x;
    int f = tid & 63, q = tid >> 6;      // q in 0..7, 8 rows each
    for (int idx = tid; idx < 4096; idx += 512) {
        int k = idx >> 6, j = idx & 63;
        W0s[k * 64 + j] = make_float4(Whh0[j * 64 + k], Whh0[(j + 64) * 64 + k],
                                      Whh0[(j + 128) * 64 + k], Whh0[(j + 192) * 64 + k]);
        W1i[k * 64 + j] = make_float4(Wih1[j * 64 + k], Wih1[(j + 64) * 64 + k],
                                      Wih1[(j + 128) * 64 + k], Wih1[(j + 192) * 64 + k]);
        W1h[k * 64 + j] = make_float4(Whh1[j * 64 + k], Whh1[(j + 64) * 64 + k],
                                      Whh1[(j + 128) * 64 + k], Whh1[(j + 192) * 64 + k]);
    }
    for (int idx = tid; idx < 4096; idx += 512) { h0s[idx] = 0.f; h1s[idx] = 0.f; }
    unsigned long long b1xy = pack2(bih1[f] + bhh1[f], bih1[64 + f] + bhh1[64 + f]);
    unsigned long long b1zw = pack2(bih1[128 + f] + bhh1[128 + f],
                                    bih1[192 + f] + bhh1[192 + f]);
    float c0[8], c1[8];
    #pragma unroll
    for (int i = 0; i < 8; i++) { c0[i] = 0.f; c1[i] = 0.f; }
    int row0 = blockIdx.x * 64;
    __syncthreads();
    for (int t = 0; t < T; t++) {
        const float* Xgt = d_Xg + ((size_t)t * n + row0) * 256;
        // prefetch this step's x-gates into registers (hidden under mm64 below)
        float xg[8][4];
        #pragma unroll
        for (int i = 0; i < 8; i++) {
            bool ok = (row0 + q * 8 + i) < n;
            const float* p = Xgt + (q * 8 + i) * 256;
            xg[i][0] = ok ? p[f] : 0.f;
            xg[i][1] = ok ? p[64 + f] : 0.f;
            xg[i][2] = ok ? p[128 + f] : 0.f;
            xg[i][3] = ok ? p[192 + f] : 0.f;
        }
        // ---- layer 0: g = h0 @ Whh0^T ----
        unsigned long long gxy[8], gzw[8];
        #pragma unroll
        for (int i = 0; i < 8; i++) { gxy[i] = 0ULL; gzw[i] = 0ULL; }
        mm64(W0s, h0s, q, f, gxy, gzw);
        __syncthreads();  // reads of h0s done before overwrite
        #pragma unroll
        for (int i = 0; i < 8; i++) {
            float gi, gf, gg, go;
            unpack2(gi, gf, gxy[i]);
            unpack2(gg, go, gzw[i]);
            float zi = xg[i][0] + gi, zf = xg[i][1] + gf;
            float zg = xg[i][2] + gg, zo = xg[i][3] + go;
            float cn = sig_fast(zf) * c0[i] + sig_fast(zi) * tanh_fast(zg);
            c0[i] = cn;
            h0s[(q * 8 + i) * 64 + f] = sig_fast(zo) * tanh_fast(cn);
        }
        __syncthreads();  // h0 ready for layer 1
        // ---- layer 1: g = h0 @ Wih1^T + h1 @ Whh1^T + b1 ----
        #pragma unroll
        for (int i = 0; i < 8; i++) { gxy[i] = b1xy; gzw[i] = b1zw; }
        mm64(W1i, h0s, q, f, gxy, gzw);
        mm64(W1h, h1s, q, f, gxy, gzw);
        __syncthreads();  // reads of h1s done before overwrite
        #pragma unroll
        for (int i = 0; i < 8; i++) {
            float gi, gf, gg, go;
            unpack2(gi, gf, gxy[i]);
            unpack2(gg, go, gzw[i]);
            float cn = sig_fast(gf) * c1[i] + sig_fast(gi) * tanh_fast(gg);
            c1[i] = cn;
            h1s[(q * 8 + i) * 64 + f] = sig_fast(go) * tanh_fast(cn);
        }
        __syncthreads();  // h1 ready for next t
    }
    #pragma unroll
    for (int i = 0; i < 8; i++) {
        int grow = row0 + q * 8 + i;
        if (grow < n) d_hlast[(size_t)grow * 64 + f] = h1s[(q * 8 + i) * 64 + f];
    }
}

// ---- head: out = relu(h_last @ fc1 + b1) @ fc2 + b2 ----
__global__ void k_head(const float* __restrict__ f1W, const float* __restrict__ f1b,
                       const float* __restrict__ f2W, const float* __restrict__ f2b,
                       float* __restrict__ out, int n) {
    int warp = threadIdx.x >> 5, lane = threadIdx.x & 31;
    int row = blockIdx.x * 4 + warp;
    if (row >= n) return;
    const float* hr = d_hlast + (size_t)row * 64;
    float acc = f1b[lane];
    #pragma unroll 8
    for (int k = 0; k < 64; k++) acc = fmaf(hr[k], f1W[k * 32 + lane], acc);
    float v = fmaxf(acc, 0.f) * f2W[lane];
    #pragma unroll
    for (int o = 16; o; o >>= 1) v += __shfl_xor_sync(0xffffffffu, v, o);
    if (lane == 0) out[row] = v + f2b[0];
}

// ---------------- launch ----------------
extern "C" void kernel_launch(void* const* d_in, const int* in_sizes, int n_in,
                              void* d_out, int out_size) {
    const float* x    = (const float*)d_in[0];
    const void*  ei   = d_in[1];               // int32 or int64, detected on device
    const float* ew   = (const float*)d_in[2];
    const float* Win  = (const float*)d_in[3];
    const float* bin  = (const float*)d_in[4];
    const float* gW   = (const float*)d_in[5];
    const float* gb   = (const float*)d_in[6];
    const float* lng  = (const float*)d_in[7];
    const float* lnb  = (const float*)d_in[8];
    const float* Wih0 = (const float*)d_in[9];
    const float* Whh0 = (const float*)d_in[10];
    const float* bih0 = (const float*)d_in[11];
    const float* bhh0 = (const float*)d_in[12];
    const float* Wih1 = (const float*)d_in[13];
    const float* Whh1 = (const float*)d_in[14];
    const float* bih1 = (const float*)d_in[15];
    const float* bhh1 = (const float*)d_in[16];
    const float* f1W  = (const float*)d_in[17];
    const float* f1b  = (const float*)d_in[18];
    const float* f2W  = (const float*)d_in[19];
    const float* f2b  = (const float*)d_in[20];
    float* out = (float*)d_out;

    // runtime shapes (clamped to static capacity)
    int n = out_size;                         // B*N with B=1
    if (n > MAXN) n = MAXN;
    int e = in_sizes[2];                      // edge count from edge_weight
    if (e > MAXE) e = MAXE;
    int fin = in_sizes[3] / 64;               // W_in: (F_IN, 64)
    if (fin > 16) fin = 16;
    int rows = in_sizes[0] / (fin > 0 ? fin : 1);  // T * N
    if (rows > MAXR) rows = MAXR;
    int T = rows / (n > 0 ? n : 1);
    if (T > MAXT) T = MAXT;
    int ngcn = in_sizes[5] / 4096;            // gcn_W: (L, 64, 64)

    cudaFuncSetAttribute(k_gates, cudaFuncAttributeMaxDynamicSharedMemorySize, GATES_SMEM);
    cudaFuncSetAttribute(k_lstm, cudaFuncAttributeMaxDynamicSharedMemorySize, LSTM_SMEM);

    // side stream + events, lazily created once (resource creation only — the
    // captured/executed GPU work is identical on every call)
    static cudaStream_t s2 = 0;
    static cudaEvent_t evF = 0, evJ = 0;
    if (s2 == 0) {
        cudaStreamCreateWithFlags(&s2, cudaStreamNonBlocking);
        cudaEventCreateWithFlags(&evF, cudaEventDisableTiming);
        cudaEventCreateWithFlags(&evJ, cudaEventDisableTiming);
    }

    // fork: CSR build on s2, projgemm on main stream (fully independent)
    cudaEventRecord(evF, 0);
    cudaStreamWaitEvent(s2, evF, 0);
    k_init<<<(n + 255) / 256, 256, 0, s2>>>((const int*)ei, n, e);
    k_deg<<<(e + 255) / 256, 256, 0, s2>>>(ei, ew, n, e);
    k_scan2<<<1, 1024, 0, s2>>>(n);
    k_fill<<<(e + 255) / 256, 256, 0, s2>>>(ei, ew, n, e);
    cudaEventRecord(evJ, s2);

    // fused input projection + GCN layer-0 GEMM (main stream, overlaps CSR)
    k_projgemm<<<(rows + 63) / 64, 256>>>(x, Win, bin, gW, rows, fin, ngcn > 0 ? 1 : 0);

    // join: first aggregation needs BOTH the CSR and the projected features
    cudaStreamWaitEvent(0, evJ, 0);

    // GCN layers (quad-t aggregation — R14 best config)
    for (int l = 0; l < ngcn; l++) {
        if (l > 0) k_gemm64<<<(rows + 63) / 64, 256>>>(gW + (size_t)l * 4096, rows);
        k_gcn_agg<<<dim3(n, (T + 3) / 4), 256>>>(gb + l * 64, lng + l * 64, lnb + l * 64,
                                                 n, e, T);
    }

    // LSTM layer-0 input gates (batched over all t)
    k_gates<<<(rows + 63) / 64, 256, GATES_SMEM>>>(Wih0, bih0, bhh0, rows);
    // fused 2-layer, T-step recurrence (512 threads, 8 rows/thread — R9 config)
    k_lstm<<<(n + 63) / 64, 512, LSTM_SMEM>>>(Whh0, Wih1, Whh1, bih1, bhh1, n, T);

    // head
    k_head<<<(n + 3) / 4, 128>>>(f1W, f1b, f2W, f2b, out, n);
}